// round 9
// baseline (speedup 1.0000x reference)
#include <cuda_runtime.h>
#include <cstdint>

#define GRID_N   7
#define NB       2
#define NC       20
#define IS       8
#define DCH      30
#define L_BOX    5.0f
#define L_NEG    0.5f

#define TPB      256
#define WARPS    (TPB / 32)
#define MAX_BLOCKS 4096

__device__ double g_partials[MAX_BLOCKS];
__device__ unsigned int g_count = 0;

__device__ __forceinline__ float bce_t(float x) {           // 1 + exp(-|x|)
    return 1.0f + __expf(-fabsf(x));
}

__device__ __forceinline__ float box_loss_f(const float* pb, const float* gb) {
    float dx = pb[0] - gb[0];
    float dy = pb[1] - gb[1];
    float sw = sqrtf(fabsf(pb[2])) - sqrtf(gb[2]);
    float sh = sqrtf(fabsf(pb[3])) - sqrtf(gb[3]);
    return dx * dx + dy * dy + sw * sw + sh * sh;
}

__global__ void __launch_bounds__(TPB)
yolo_loss_kernel(const float* __restrict__ p, const float* __restrict__ g,
                 int ncells, float* __restrict__ out, float inv_nb) {
    const int tid  = threadIdx.x;
    const int lane = tid & 31;
    const int wid  = tid >> 5;
    const int c0   = (blockIdx.x * WARPS + wid) * 32;   // first cell of this warp's tile
    const int myCell = c0 + lane;
    const bool valid = myCell < ncells;

    float acc = 0.0f;

    // ================= per-lane box+conf loads (floats 0..9) =================
    float2 pf[5];   // p[0..9]
    float2 gf[4];   // g[0..7]
    float  conf_g = 0.0f;
    if (valid) {
        const float2* pc2 = reinterpret_cast<const float2*>(p + (size_t)myCell * DCH);
        const float2* gc2 = reinterpret_cast<const float2*>(g + (size_t)myCell * DCH);
        pf[0] = pc2[0]; pf[1] = pc2[1]; pf[2] = pc2[2]; pf[3] = pc2[3]; pf[4] = pc2[4];
        gf[0] = gc2[0]; gf[1] = gc2[1]; gf[2] = gc2[2]; gf[3] = gc2[3];
        conf_g = __ldg(g + (size_t)myCell * DCH + IS);
    }

    // ================= classification: channel-parallel streaming =================
    // 32 cells x 10 float2-pairs = 320 pairs; lane handles q = j*32+lane.
    // cls loss = sum over masked elements of [max(x,0)-x*t] + log(prod of (1+e^-|x|))
    {
        float lin = 0.0f;
        float prod = 1.0f;
        #pragma unroll
        for (int j = 0; j < 10; j++) {
            int q = j * 32 + lane;
            int cell_local = q / 10;          // 0..31
            int pair = q - 10 * cell_local;   // 0..9
            int cellIdx = c0 + cell_local;
            // mask: conf of that cell, via shuffle of per-lane conf regs
            float cf = __shfl_sync(0xffffffffu, conf_g, cell_local);
            bool m = (cf > 0.0f) && (cellIdx < ncells);

            if (cellIdx < ncells) {
                size_t off = (size_t)cellIdx * DCH + NB * 5 + 2 * pair;
                float2 a = *reinterpret_cast<const float2*>(p + off);
                float2 b = *reinterpret_cast<const float2*>(g + off);
                float linq = fmaxf(a.x, 0.f) - a.x * b.x + fmaxf(a.y, 0.f) - a.y * b.y;
                float prq  = bce_t(a.x) * bce_t(a.y);
                lin  += m ? linq : 0.0f;
                prod *= m ? prq : 1.0f;
            }
        }
        acc += lin + __logf(prod);   // prod <= 2^20: no overflow
    }

    // ================= per-cell box / conf =================
    if (valid) {
        float2 pconf = pf[4];        // p[8], p[9]
        if (conf_g > 0.0f) {
            float pv[IS] = {pf[0].x, pf[0].y, pf[1].x, pf[1].y,
                            pf[2].x, pf[2].y, pf[3].x, pf[3].y};
            float gv[IS] = {gf[0].x, gf[0].y, gf[1].x, gf[1].y,
                            gf[2].x, gf[2].y, gf[3].x, gf[3].y};

            int cell = myCell % (GRID_N * GRID_N);
            float col = (float)(cell % GRID_N);
            float row = (float)(cell / GRID_N);

            float poff[NB][4], gbox[NB][4];
            #pragma unroll
            for (int b = 0; b < NB; b++) {
                poff[b][0] = __fdividef(1.0f, 1.0f + __expf(-pv[4 * b + 0]));
                poff[b][1] = __fdividef(1.0f, 1.0f + __expf(-pv[4 * b + 1]));
                poff[b][2] = pv[4 * b + 2];
                poff[b][3] = pv[4 * b + 3];
                gbox[b][0] = gv[4 * b + 0];
                gbox[b][1] = gv[4 * b + 1];
                gbox[b][2] = gv[4 * b + 2];
                gbox[b][3] = gv[4 * b + 3];
            }

            float pl[NB][4], gl[NB][4];
            #pragma unroll
            for (int b = 0; b < NB; b++) {
                float cx = (poff[b][0] + col) * (1.0f / GRID_N);
                float cy = (poff[b][1] + row) * (1.0f / GRID_N);
                float w  = poff[b][2], h = poff[b][3];
                pl[b][0] = cx - w * 0.5f; pl[b][1] = cy - h * 0.5f;
                pl[b][2] = cx + w * 0.5f; pl[b][3] = cy + h * 0.5f;
                float gx = (gbox[b][0] + col) * (1.0f / GRID_N);
                float gy = (gbox[b][1] + row) * (1.0f / GRID_N);
                float gw = gbox[b][2], gh = gbox[b][3];
                gl[b][0] = gx - gw * 0.5f; gl[b][1] = gy - gh * 0.5f;
                gl[b][2] = gx + gw * 0.5f; gl[b][3] = gy + gh * 0.5f;
            }

            float iou[NB][NB];
            #pragma unroll
            for (int pi = 0; pi < NB; pi++) {
                #pragma unroll
                for (int gi = 0; gi < NB; gi++) {
                    float ltx = fmaxf(pl[pi][0], gl[gi][0]);
                    float lty = fmaxf(pl[pi][1], gl[gi][1]);
                    float rbx = fminf(pl[pi][2], gl[gi][2]);
                    float rby = fminf(pl[pi][3], gl[gi][3]);
                    float wx = fmaxf(rbx - ltx, 0.0f);
                    float wy = fmaxf(rby - lty, 0.0f);
                    float inter = wx * wy;
                    float aa = (pl[pi][2] - pl[pi][0]) * (pl[pi][3] - pl[pi][1]);
                    float ab = (gl[gi][2] - gl[gi][0]) * (gl[gi][3] - gl[gi][1]);
                    iou[pi][gi] = __fdividef(inter, aa + ab - inter + 1e-7f);
                }
            }

            int ind0 = (iou[1][0] > iou[0][0]) ? 1 : 0;
            int ind1 = (iou[1][1] > iou[0][1]) ? 1 : 0;

            bool same_g = (gbox[0][0] == gbox[1][0]) && (gbox[0][1] == gbox[1][1]) &&
                          (gbox[0][2] == gbox[1][2]) && (gbox[0][3] == gbox[1][3]);
            bool same_ind = (ind0 == ind1);

            float box_cell;
            if (same_g) {
                box_cell = box_loss_f(poff[ind0], gbox[0]);
            } else if (same_ind) {
                box_cell = box_loss_f(poff[0], gbox[0]) + box_loss_f(poff[1], gbox[1]);
            } else {
                box_cell = box_loss_f(poff[ind0], gbox[0]) + box_loss_f(poff[ind1], gbox[1]);
            }

            float conf_cell;
            if (same_g) {
                float x = ind1 ? pconf.y : pconf.x;
                conf_cell = fmaxf(x, 0.f) - x + __logf(bce_t(x));
            } else {
                conf_cell = fmaxf(pconf.x, 0.f) - pconf.x + fmaxf(pconf.y, 0.f) - pconf.y
                          + __logf(bce_t(pconf.x) * bce_t(pconf.y));
            }

            acc += L_BOX * box_cell + conf_cell;
        } else {
            acc += L_NEG * (fmaxf(pconf.x, 0.f) + fmaxf(pconf.y, 0.f)
                            + __logf(bce_t(pconf.x) * bce_t(pconf.y)));
        }
    }

    // ---- deterministic block reduction ----
    #pragma unroll
    for (int o = 16; o > 0; o >>= 1)
        acc += __shfl_down_sync(0xffffffffu, acc, o);

    __shared__ float warp_sums[WARPS];
    if (lane == 0) warp_sums[wid] = acc;
    __syncthreads();

    if (tid == 0) {
        float v = 0.0f;
        #pragma unroll
        for (int w = 0; w < WARPS; w++) v += warp_sums[w];
        g_partials[blockIdx.x] = (double)v;
    }

    // ---- last-block finalization (deterministic fixed-order sum) ----
    __shared__ bool isLast;
    if (tid == 0) {
        __threadfence();
        unsigned int v = atomicAdd(&g_count, 1u);
        isLast = (v == gridDim.x - 1);
    }
    __syncthreads();

    if (isLast) {
        __shared__ double sh[TPB];
        double s = 0.0;
        for (int i = tid; i < (int)gridDim.x; i += TPB)
            s += g_partials[i];
        sh[tid] = s;
        __syncthreads();
        #pragma unroll
        for (int strideR = TPB / 2; strideR > 0; strideR >>= 1) {
            if (tid < strideR) sh[tid] += sh[tid + strideR];
            __syncthreads();
        }
        if (tid == 0) {
            out[0] = (float)(sh[0] * (double)inv_nb);
            g_count = 0;   // reset for next graph replay
        }
    }
}

extern "C" void kernel_launch(void* const* d_in, const int* in_sizes, int n_in,
                              void* d_out, int out_size) {
    const float* p = (const float*)d_in[0];
    const float* g = (const float*)d_in[1];
    float* out = (float*)d_out;

    int ncells = in_sizes[0] / DCH;                 // B * 49
    int batch  = ncells / (GRID_N * GRID_N);        // B
    int cellsPerBlock = 32 * WARPS;
    int nblocks = (ncells + cellsPerBlock - 1) / cellsPerBlock;
    if (nblocks > MAX_BLOCKS) nblocks = MAX_BLOCKS; // never hit for this size

    yolo_loss_kernel<<<nblocks, TPB>>>(p, g, ncells, out, 1.0f / (float)batch);
}

// round 10
// speedup vs baseline: 1.3833x; 1.3833x over previous
#include <cuda_runtime.h>
#include <cstdint>

#define GRID_N   7
#define NB       2
#define NC       20
#define IS       8
#define DCH      30
#define L_BOX    5.0f
#define L_NEG    0.5f

#define TPB      64
#define WARPS    (TPB / 32)
#define NBLOCKS  1036           // 148 SMs x 7 blocks (30.7KB smem each) = one wave
#define MAX_BLOCKS 2048

// per tile: 32 cells x 30 floats = 960 floats = 240 float4 per tensor
#define T4       240

__device__ double g_partials[MAX_BLOCKS];
__device__ unsigned int g_count = 0;

__device__ __forceinline__ void cp_async16(uint32_t dst, const void* src) {
    asm volatile("cp.async.cg.shared.global [%0], [%1], 16;\n" :: "r"(dst), "l"(src));
}
__device__ __forceinline__ void cp_commit() {
    asm volatile("cp.async.commit_group;\n" ::: "memory");
}
__device__ __forceinline__ void cp_wait1() {
    asm volatile("cp.async.wait_group 1;\n" ::: "memory");
}
__device__ __forceinline__ void cp_wait0() {
    asm volatile("cp.async.wait_group 0;\n" ::: "memory");
}

__device__ __forceinline__ float bce_t(float x) {           // 1 + exp(-|x|)
    return 1.0f + __expf(-fabsf(x));
}

__device__ __forceinline__ float box_loss_f(const float* pb, const float* gb) {
    float dx = pb[0] - gb[0];
    float dy = pb[1] - gb[1];
    float sw = sqrtf(fabsf(pb[2])) - sqrtf(gb[2]);
    float sh = sqrtf(fabsf(pb[3])) - sqrtf(gb[3]);
    return dx * dx + dy * dy + sw * sw + sh * sh;
}

// pc/gc point at one cell's 30 floats (smem in fast path, gmem in tail path).
__device__ __forceinline__ float cell_loss(const float* __restrict__ pc,
                                           const float* __restrict__ gc,
                                           int cellIdx) {
    const float2* pc2 = reinterpret_cast<const float2*>(pc);
    const float2* gc2 = reinterpret_cast<const float2*>(gc);
    float2 pb0 = pc2[0], pb1 = pc2[1], pb2v = pc2[2], pb3 = pc2[3];
    float2 gb0 = gc2[0], gb1 = gc2[1], gb2v = gc2[2], gb3 = gc2[3];
    float2 pconf = pc2[4];
    float2 gconf = gc2[4];

    if (gconf.x > 0.0f) {
        float pv[IS] = {pb0.x, pb0.y, pb1.x, pb1.y, pb2v.x, pb2v.y, pb3.x, pb3.y};
        float gv[IS] = {gb0.x, gb0.y, gb1.x, gb1.y, gb2v.x, gb2v.y, gb3.x, gb3.y};

        // ---- classification: two independent (lin, prod) chains ----
        const float2* pcl2 = reinterpret_cast<const float2*>(pc + NB * 5);
        const float2* gcl2 = reinterpret_cast<const float2*>(gc + NB * 5);
        float lin0 = 0.0f, lin1 = 0.0f;
        float prod0 = 1.0f, prod1 = 1.0f;
        #pragma unroll
        for (int i = 0; i < 5; i++) {
            float2 a = pcl2[i];
            float2 b = gcl2[i];
            lin0  += fmaxf(a.x, 0.f) - a.x * b.x + fmaxf(a.y, 0.f) - a.y * b.y;
            prod0 *= bce_t(a.x) * bce_t(a.y);
            float2 c = pcl2[i + 5];
            float2 d = gcl2[i + 5];
            lin1  += fmaxf(c.x, 0.f) - c.x * d.x + fmaxf(c.y, 0.f) - c.y * d.y;
            prod1 *= bce_t(c.x) * bce_t(c.y);
        }
        float cls = (lin0 + lin1) + __logf(prod0 * prod1);

        int cell = cellIdx % (GRID_N * GRID_N);
        float col = (float)(cell % GRID_N);
        float row = (float)(cell / GRID_N);

        float poff[NB][4], gbox[NB][4];
        #pragma unroll
        for (int b = 0; b < NB; b++) {
            poff[b][0] = __fdividef(1.0f, 1.0f + __expf(-pv[4 * b + 0]));
            poff[b][1] = __fdividef(1.0f, 1.0f + __expf(-pv[4 * b + 1]));
            poff[b][2] = pv[4 * b + 2];
            poff[b][3] = pv[4 * b + 3];
            gbox[b][0] = gv[4 * b + 0];
            gbox[b][1] = gv[4 * b + 1];
            gbox[b][2] = gv[4 * b + 2];
            gbox[b][3] = gv[4 * b + 3];
        }

        float pl[NB][4], gl[NB][4];
        #pragma unroll
        for (int b = 0; b < NB; b++) {
            float cx = (poff[b][0] + col) * (1.0f / GRID_N);
            float cy = (poff[b][1] + row) * (1.0f / GRID_N);
            float w  = poff[b][2], h = poff[b][3];
            pl[b][0] = cx - w * 0.5f; pl[b][1] = cy - h * 0.5f;
            pl[b][2] = cx + w * 0.5f; pl[b][3] = cy + h * 0.5f;
            float gx = (gbox[b][0] + col) * (1.0f / GRID_N);
            float gy = (gbox[b][1] + row) * (1.0f / GRID_N);
            float gw = gbox[b][2], gh = gbox[b][3];
            gl[b][0] = gx - gw * 0.5f; gl[b][1] = gy - gh * 0.5f;
            gl[b][2] = gx + gw * 0.5f; gl[b][3] = gy + gh * 0.5f;
        }

        float iou[NB][NB];
        #pragma unroll
        for (int pi = 0; pi < NB; pi++) {
            #pragma unroll
            for (int gi = 0; gi < NB; gi++) {
                float ltx = fmaxf(pl[pi][0], gl[gi][0]);
                float lty = fmaxf(pl[pi][1], gl[gi][1]);
                float rbx = fminf(pl[pi][2], gl[gi][2]);
                float rby = fminf(pl[pi][3], gl[gi][3]);
                float wx = fmaxf(rbx - ltx, 0.0f);
                float wy = fmaxf(rby - lty, 0.0f);
                float inter = wx * wy;
                float aa = (pl[pi][2] - pl[pi][0]) * (pl[pi][3] - pl[pi][1]);
                float ab = (gl[gi][2] - gl[gi][0]) * (gl[gi][3] - gl[gi][1]);
                iou[pi][gi] = __fdividef(inter, aa + ab - inter + 1e-7f);
            }
        }

        int ind0 = (iou[1][0] > iou[0][0]) ? 1 : 0;
        int ind1 = (iou[1][1] > iou[0][1]) ? 1 : 0;

        bool same_g = (gbox[0][0] == gbox[1][0]) && (gbox[0][1] == gbox[1][1]) &&
                      (gbox[0][2] == gbox[1][2]) && (gbox[0][3] == gbox[1][3]);
        bool same_ind = (ind0 == ind1);

        float box_cell;
        if (same_g) {
            box_cell = box_loss_f(poff[ind0], gbox[0]);
        } else if (same_ind) {
            box_cell = box_loss_f(poff[0], gbox[0]) + box_loss_f(poff[1], gbox[1]);
        } else {
            box_cell = box_loss_f(poff[ind0], gbox[0]) + box_loss_f(poff[ind1], gbox[1]);
        }

        float conf_cell;
        if (same_g) {
            float x = ind1 ? pconf.y : pconf.x;
            conf_cell = fmaxf(x, 0.f) - x + __logf(bce_t(x));
        } else {
            conf_cell = fmaxf(pconf.x, 0.f) - pconf.x + fmaxf(pconf.y, 0.f) - pconf.y
                      + __logf(bce_t(pconf.x) * bce_t(pconf.y));
        }

        return L_BOX * box_cell + conf_cell + cls;
    } else {
        return L_NEG * (fmaxf(pconf.x, 0.f) + fmaxf(pconf.y, 0.f)
                        + __logf(bce_t(pconf.x) * bce_t(pconf.y)));
    }
}

// issue one tile's staging loads (p then g), lane-partitioned, and commit.
// 240 float4 per tensor = 7.5 warp-steps: 7 full + half-step on lane<16.
__device__ __forceinline__ void stage_tile(uint32_t dst, const float* __restrict__ p,
                                           const float* __restrict__ g,
                                           int tile, int lane) {
    const float4* psrc = reinterpret_cast<const float4*>(p + (size_t)tile * 32 * DCH) + lane;
    const float4* gsrc = reinterpret_cast<const float4*>(g + (size_t)tile * 32 * DCH) + lane;
    uint32_t pd = dst + lane * 16;
    uint32_t gd = dst + T4 * 16 + lane * 16;
    #pragma unroll
    for (int k = 0; k < 7; k++) {
        cp_async16(pd + k * 512, psrc + 32 * k);
        cp_async16(gd + k * 512, gsrc + 32 * k);
    }
    if (lane < 16) {
        cp_async16(pd + 7 * 512, psrc + 224);
        cp_async16(gd + 7 * 512, gsrc + 224);
    }
    cp_commit();
}

__global__ void __launch_bounds__(TPB)
yolo_loss_kernel(const float* __restrict__ p, const float* __restrict__ g,
                 int ncells, float* __restrict__ out, float inv_nb) {
    // per-warp double buffer: [stage][p(240) | g(240)] float4
    __shared__ float4 sbuf[WARPS][2][2 * T4];    // 2 * 2 * 480 * 16 = 30720 B

    const int tid  = threadIdx.x;
    const int lane = tid & 31;
    const int wid  = tid >> 5;
    const int warpGlobal = blockIdx.x * WARPS + wid;
    const int nwarps = gridDim.x * WARPS;
    const int ntiles = ncells >> 5;              // full 32-cell tiles

    uint32_t bufs[2];
    bufs[0] = (uint32_t)__cvta_generic_to_shared(&sbuf[wid][0][0]);
    bufs[1] = (uint32_t)__cvta_generic_to_shared(&sbuf[wid][1][0]);

    float acc = 0.0f;

    // ---- prologue: prefetch first tile ----
    int t = warpGlobal;
    if (t < ntiles) stage_tile(bufs[0], p, g, t, lane);

    int cur = 0;
    for (; t < ntiles; t += nwarps) {
        int tn = t + nwarps;
        bool pf = (tn < ntiles);
        if (pf) stage_tile(bufs[cur ^ 1], p, g, tn, lane);

        if (pf) cp_wait1(); else cp_wait0();
        __syncwarp();

        const float* base = reinterpret_cast<const float*>(&sbuf[wid][cur][0]);
        const float* pcell = base + lane * DCH;
        const float* gcell = base + 4 * T4 + lane * DCH;    // g starts after 960 floats
        acc += cell_loss(pcell, gcell, t * 32 + lane);

        __syncwarp();          // all lanes done reading before buffer is reused
        cur ^= 1;
    }

    // ---- tail cells (ncells not multiple of 32): warp 0 of block 0 ----
    if (blockIdx.x == 0 && wid == 0) {
        int idx = ntiles * 32 + lane;
        if (idx < ncells)
            acc += cell_loss(p + (size_t)idx * DCH, g + (size_t)idx * DCH, idx);
    }

    // ---- deterministic block reduction ----
    #pragma unroll
    for (int o = 16; o > 0; o >>= 1)
        acc += __shfl_down_sync(0xffffffffu, acc, o);

    __shared__ float warp_sums[WARPS];
    if (lane == 0) warp_sums[wid] = acc;
    __syncthreads();

    if (tid == 0) {
        float v = 0.0f;
        #pragma unroll
        for (int w = 0; w < WARPS; w++) v += warp_sums[w];
        g_partials[blockIdx.x] = (double)v;
    }

    // ---- last-block finalization (deterministic fixed-order sum) ----
    __shared__ bool isLast;
    if (tid == 0) {
        __threadfence();
        unsigned int v = atomicAdd(&g_count, 1u);
        isLast = (v == gridDim.x - 1);
    }
    __syncthreads();

    if (isLast) {
        __shared__ double sh[TPB];
        double s = 0.0;
        for (int i = tid; i < (int)gridDim.x; i += TPB)
            s += g_partials[i];
        sh[tid] = s;
        __syncthreads();
        #pragma unroll
        for (int strideR = TPB / 2; strideR > 0; strideR >>= 1) {
            if (tid < strideR) sh[tid] += sh[tid + strideR];
            __syncthreads();
        }
        if (tid == 0) {
            out[0] = (float)(sh[0] * (double)inv_nb);
            g_count = 0;   // reset for next graph replay
        }
    }
}

extern "C" void kernel_launch(void* const* d_in, const int* in_sizes, int n_in,
                              void* d_out, int out_size) {
    const float* p = (const float*)d_in[0];
    const float* g = (const float*)d_in[1];
    float* out = (float*)d_out;

    int ncells = in_sizes[0] / DCH;                 // B * 49
    int batch  = ncells / (GRID_N * GRID_N);        // B
    int ntiles = ncells >> 5;

    int nblocks = NBLOCKS;
    int needed = (ntiles + WARPS - 1) / WARPS;
    if (needed < 1) needed = 1;
    if (nblocks > needed) nblocks = needed;         // small inputs: shrink grid
    if (nblocks > MAX_BLOCKS) nblocks = MAX_BLOCKS;

    yolo_loss_kernel<<<nblocks, TPB>>>(p, g, ncells, out, 1.0f / (float)batch);
}